// round 12
// baseline (speedup 1.0000x reference)
#include <cuda_runtime.h>
#include <cstdint>
#include <math.h>

typedef unsigned long long ull;

#define Bv 32
#define Lv 1024
#define Hv 512
#define NGROUP 8
#define CPG 16
#define WS 512

// ---------------- device scratch (no cudaMalloc allowed) ----------------
__device__ float g_pre[(size_t)Lv * Bv * 1536];   // [t][b][0..511]=r-pre, [512..1023]=z-pre, [1024..1535]=c-pre
__device__ float g_h [Bv * Hv];
__device__ float g_rh[Bv * Hv];
__device__ unsigned int g_flag[NGROUP * CPG * 32];   // one flag per CTA, own 128B line

// ---------------- f32x2 helpers ----------------
__device__ __forceinline__ ull splat2(float x) {
    ull r; asm("mov.b64 %0, {%1, %1};" : "=l"(r) : "f"(x)); return r;
}
__device__ __forceinline__ float2 unpack2(ull v) {
    float2 f; asm("mov.b64 {%0, %1}, %2;" : "=f"(f.x), "=f"(f.y) : "l"(v)); return f;
}
__device__ __forceinline__ void ffma2(ull& d, ull a, ull b) {
    asm("fma.rn.f32x2 %0, %1, %2, %0;" : "+l"(d) : "l"(a), "l"(b));
}
__device__ __forceinline__ float fast_sigmoid(float x) {
    x = fminf(fmaxf(x, -30.0f), 30.0f);
    return 1.0f / (1.0f + __expf(-x));
}
__device__ __forceinline__ float fast_tanh(float x) {
    x = fminf(fmaxf(x, -15.0f), 15.0f);
    float e = __expf(2.0f * x);
    return (e - 1.0f) / (e + 1.0f);
}

// pairwise named barrier: the two warps of one row-group (64 threads)
#define BARW(id) asm volatile("bar.sync %0, 64;" :: "r"(id) : "memory")

// ---------------- kernel 1: projection GEMM (fp32, f32x2) ----------------
__global__ void __launch_bounds__(256) gemm_pre(const float* __restrict__ x,
                                                const float* __restrict__ W_ru,
                                                const float* __restrict__ W_c,
                                                const float* __restrict__ b_ru,
                                                const float* __restrict__ b_c) {
    __shared__ float As[2][64 * 36];
    __shared__ float Bs[2][32 * 64];
    const int tid = threadIdx.x;
    const int n0 = blockIdx.x * 64;
    const int m0 = blockIdx.y * 64;

    const float* Wsrc = (n0 < 1024) ? (W_ru + (size_t)n0 * 1024 + 512)
                                    : (W_c + (size_t)(n0 - 1024) * 1024 + 512);

    const int arow = tid >> 3, ac = (tid & 7) * 4;
    const float* Ap0 = x + (size_t)(m0 + arow) * 512 + ac;
    const int bn = tid & 63, bk = (tid >> 6) * 4;
    const float* Bp0 = Wsrc + (size_t)bn * 1024 + bk;

    const int tx = tid & 15, ty = tid >> 4;

    ull acc[4][2];
#pragma unroll
    for (int i = 0; i < 4; i++) { acc[i][0] = 0ull; acc[i][1] = 0ull; }

    float4 ra0 = *(const float4*)(Ap0);
    float4 ra1 = *(const float4*)(Ap0 + 32 * 512);
    float4 rb0 = *(const float4*)(Bp0);
    float4 rb1 = *(const float4*)(Bp0 + 16);

    *(float4*)&As[0][arow * 36 + ac] = ra0;
    *(float4*)&As[0][(arow + 32) * 36 + ac] = ra1;
    Bs[0][(bk + 0) * 64 + bn] = rb0.x; Bs[0][(bk + 1) * 64 + bn] = rb0.y;
    Bs[0][(bk + 2) * 64 + bn] = rb0.z; Bs[0][(bk + 3) * 64 + bn] = rb0.w;
    Bs[0][(bk + 16) * 64 + bn] = rb1.x; Bs[0][(bk + 17) * 64 + bn] = rb1.y;
    Bs[0][(bk + 18) * 64 + bn] = rb1.z; Bs[0][(bk + 19) * 64 + bn] = rb1.w;
    __syncthreads();

    for (int kt = 0; kt < 16; kt++) {
        const int cur = kt & 1;
        if (kt < 15) {
            const float* ap = Ap0 + (kt + 1) * 32;
            ra0 = *(const float4*)(ap);
            ra1 = *(const float4*)(ap + 32 * 512);
            const float* bp = Bp0 + (kt + 1) * 32;
            rb0 = *(const float4*)(bp);
            rb1 = *(const float4*)(bp + 16);
        }
        const float* Arow = &As[cur][ty * 4 * 36];
        const float* Bbase = &Bs[cur][0];
#pragma unroll
        for (int kk = 0; kk < 32; kk++) {
            float av0 = Arow[kk], av1 = Arow[36 + kk], av2 = Arow[72 + kk], av3 = Arow[108 + kk];
            const ull* Bq = (const ull*)(Bbase + kk * 64);
            ull b0 = Bq[tx * 2], b1 = Bq[tx * 2 + 1];
            ull s0 = splat2(av0), s1 = splat2(av1), s2 = splat2(av2), s3 = splat2(av3);
            ffma2(acc[0][0], s0, b0); ffma2(acc[0][1], s0, b1);
            ffma2(acc[1][0], s1, b0); ffma2(acc[1][1], s1, b1);
            ffma2(acc[2][0], s2, b0); ffma2(acc[2][1], s2, b1);
            ffma2(acc[3][0], s3, b0); ffma2(acc[3][1], s3, b1);
        }
        if (kt < 15) {
            const int nb = (kt + 1) & 1;
            *(float4*)&As[nb][arow * 36 + ac] = ra0;
            *(float4*)&As[nb][(arow + 32) * 36 + ac] = ra1;
            Bs[nb][(bk + 0) * 64 + bn] = rb0.x; Bs[nb][(bk + 1) * 64 + bn] = rb0.y;
            Bs[nb][(bk + 2) * 64 + bn] = rb0.z; Bs[nb][(bk + 3) * 64 + bn] = rb0.w;
            Bs[nb][(bk + 16) * 64 + bn] = rb1.x; Bs[nb][(bk + 17) * 64 + bn] = rb1.y;
            Bs[nb][(bk + 18) * 64 + bn] = rb1.z; Bs[nb][(bk + 19) * 64 + bn] = rb1.w;
        }
        __syncthreads();
    }

    const float* bias = (n0 < 1024) ? (b_ru + n0) : (b_c + (n0 - 1024));
    const float4 bv = *(const float4*)&bias[tx * 4];
#pragma unroll
    for (int i = 0; i < 4; i++) {
        int m = m0 + ty * 4 + i;
        int bb = m >> 10, tt = m & 1023;
        float2 f0 = unpack2(acc[i][0]);
        float2 f1 = unpack2(acc[i][1]);
        float4 o = make_float4(f0.x + bv.x, f0.y + bv.y, f1.x + bv.z, f1.y + bv.w);
        *(float4*)&g_pre[((size_t)tt * 32 + bb) * 1536 + n0 + tx * 4] = o;
    }
}

// ---------------- group barrier ----------------
__device__ __forceinline__ void bar_signal(int grp, int c, unsigned target) {
    asm volatile("st.release.gpu.u32 [%0], %1;"
                 :: "l"(g_flag + ((size_t)(grp * CPG + c) * 32)), "r"(target) : "memory");
}
__device__ __forceinline__ void bar_poll(int grp, unsigned target) {
    if (threadIdx.x < CPG) {
        const unsigned* fp = g_flag + ((size_t)(grp * CPG + threadIdx.x) * 32);
        unsigned v;
        do {
            asm volatile("ld.acquire.gpu.u32 %0, [%1];" : "=r"(v) : "l"(fp) : "memory");
        } while ((int)(v - target) < 0);
    }
    __syncthreads();
}

// ---------------- scan microkernel ----------------
// warp tile: 4 rows x 4 batches over a 256-wide k-half; lane covers 4 consecutive
// floats at 4*l (LDS.128, conflict-free), 2 iterations of stride 128.
__device__ __forceinline__ void mk44(const float* __restrict__ wb,
                                     const float* __restrict__ hb, ull* a) {
#pragma unroll
    for (int i = 0; i < 2; i++) {
        const int off = 128 * i;
        ulonglong2 w0 = *(const ulonglong2*)(wb + off);
        ulonglong2 w1 = *(const ulonglong2*)(wb + WS + off);
        ulonglong2 w2 = *(const ulonglong2*)(wb + 2 * WS + off);
        ulonglong2 w3 = *(const ulonglong2*)(wb + 3 * WS + off);
        ulonglong2 h0 = *(const ulonglong2*)(hb + off);
        ulonglong2 h1 = *(const ulonglong2*)(hb + WS + off);
        ulonglong2 h2 = *(const ulonglong2*)(hb + 2 * WS + off);
        ulonglong2 h3 = *(const ulonglong2*)(hb + 3 * WS + off);
        // .x sweep (16 instr), then .y sweep: same-acc writes are 16 apart
        ffma2(a[0],  w0.x, h0.x); ffma2(a[1],  w0.x, h1.x); ffma2(a[2],  w0.x, h2.x); ffma2(a[3],  w0.x, h3.x);
        ffma2(a[4],  w1.x, h0.x); ffma2(a[5],  w1.x, h1.x); ffma2(a[6],  w1.x, h2.x); ffma2(a[7],  w1.x, h3.x);
        ffma2(a[8],  w2.x, h0.x); ffma2(a[9],  w2.x, h1.x); ffma2(a[10], w2.x, h2.x); ffma2(a[11], w2.x, h3.x);
        ffma2(a[12], w3.x, h0.x); ffma2(a[13], w3.x, h1.x); ffma2(a[14], w3.x, h2.x); ffma2(a[15], w3.x, h3.x);
        ffma2(a[0],  w0.y, h0.y); ffma2(a[1],  w0.y, h1.y); ffma2(a[2],  w0.y, h2.y); ffma2(a[3],  w0.y, h3.y);
        ffma2(a[4],  w1.y, h0.y); ffma2(a[5],  w1.y, h1.y); ffma2(a[6],  w1.y, h2.y); ffma2(a[7],  w1.y, h3.y);
        ffma2(a[8],  w2.y, h0.y); ffma2(a[9],  w2.y, h1.y); ffma2(a[10], w2.y, h2.y); ffma2(a[11], w2.y, h3.y);
        ffma2(a[12], w3.y, h0.y); ffma2(a[13], w3.y, h1.y); ffma2(a[14], w3.y, h2.y); ffma2(a[15], w3.y, h3.y);
    }
}
// value-splitting butterfly: 16 values over 32 lanes -> every lane holds value (l>>1)&15
__device__ __forceinline__ float reduce16(const ull* a, int l) {
    float vals[16];
#pragma unroll
    for (int v = 0; v < 16; v++) { float2 f = unpack2(a[v]); vals[v] = f.x + f.y; }
#pragma unroll
    for (int i = 0; i < 8; i++) {
        float send = (l & 16) ? vals[i] : vals[i + 8];
        float recv = __shfl_xor_sync(0xffffffffu, send, 16);
        vals[i] = ((l & 16) ? vals[i + 8] : vals[i]) + recv;
    }
#pragma unroll
    for (int i = 0; i < 4; i++) {
        float send = (l & 8) ? vals[i] : vals[i + 4];
        float recv = __shfl_xor_sync(0xffffffffu, send, 8);
        vals[i] = ((l & 8) ? vals[i + 4] : vals[i]) + recv;
    }
#pragma unroll
    for (int i = 0; i < 2; i++) {
        float send = (l & 4) ? vals[i] : vals[i + 2];
        float recv = __shfl_xor_sync(0xffffffffu, send, 4);
        vals[i] = ((l & 4) ? vals[i + 2] : vals[i]) + recv;
    }
    {
        float send = (l & 2) ? vals[0] : vals[1];
        float recv = __shfl_xor_sync(0xffffffffu, send, 2);
        vals[0] = ((l & 2) ? vals[1] : vals[0]) + recv;
    }
    return vals[0] + __shfl_xor_sync(0xffffffffu, vals[0], 1);
}

// ---------------- kernel 2: persistent scan, r/z/cand split ----------------
__global__ void __launch_bounds__(512, 1) scan_kernel(const float* __restrict__ W_ru,
                                                      const float* __restrict__ W_c,
                                                      const float* __restrict__ init_h,
                                                      float* __restrict__ out,
                                                      int has_last) {
    extern __shared__ float sm[];
    float* sWr = sm;                       // 32 x 512
    float* sWz = sWr + 32 * WS;            // 32 x 512
    float* sWc = sWz + 32 * WS;            // 32 x 512
    float* sh  = sWc + 32 * WS;            // 4 x 512
    float* srh = sh + 4 * WS;              // 4 x 512
    float* redR = srh + 4 * WS;            // 8 x 16
    float* redZ = redR + 128;              // 8 x 16
    float* redC = redZ + 128;              // 8 x 16
    __shared__ unsigned sBase;

    const int tid = threadIdx.x;
    const int w = tid >> 5, l = tid & 31;
    const int rg = w >> 1, kh = w & 1;
    const int grp = blockIdx.x >> 4;
    const int c   = blockIdx.x & 15;

    if (tid == 0) sBase = g_flag[(size_t)(grp * CPG + c) * 32];

    for (int i = tid; i < 32 * 128; i += 512) {
        int r = i >> 7, q = (i & 127) * 4;
        *(float4*)(sWr + r * WS + q) = *(const float4*)(W_ru + (size_t)(c * 32 + r) * 1024 + q);
        *(float4*)(sWz + r * WS + q) = *(const float4*)(W_ru + (size_t)(512 + c * 32 + r) * 1024 + q);
        *(float4*)(sWc + r * WS + q) = *(const float4*)(W_c + (size_t)(c * 32 + r) * 1024 + q);
    }
    {
        int b = tid >> 7, q = (tid & 127) * 4;
        *(float4*)(sh + b * WS + q) = *(const float4*)(init_h + (size_t)(grp * 4 + b) * 512 + q);
    }
    __syncthreads();
    const unsigned base = sBase;

    // finalizer mapping (kh==0, even lanes)
    const int oidx = (l >> 1) & 15;
    const int row_local = rg * 4 + (oidx >> 2);
    const int bat = oidx & 3;
    const int nn  = c * 32 + row_local;
    const int gbo = grp * 4 + bat;
    const bool fin = (kh == 0) && ((l & 1) == 0);
    const int ridx = rg * 16 + oidx;
    const int barid = 1 + rg;

    // microkernel bases: lane covers floats [4l, 4l+4)
    const float* wr = sWr + (rg * 4) * WS + kh * 256 + 4 * l;
    const float* wz = sWz + (rg * 4) * WS + kh * 256 + 4 * l;
    const float* wc = sWc + (rg * 4) * WS + kh * 256 + 4 * l;
    const float* hh = sh + kh * 256 + 4 * l;
    const float* rr = srh + kh * 256 + 4 * l;

    float xr = 0.f, xz = 0.f, xc = 0.f;
    if (fin) {
        const float* p = g_pre + (size_t)gbo * 1536;
        xr = __ldg(p + nn); xz = __ldg(p + 512 + nn); xc = __ldg(p + 1024 + nn);
    }

    for (int t = 0; t < Lv; t++) {
        // ---- phase R ----
        ull a[16];
#pragma unroll
        for (int i = 0; i < 16; i++) a[i] = 0ull;
        mk44(wr, hh, a);
        float totR = reduce16(a, l);
        if (kh == 1 && (l & 1) == 0) redR[ridx] = totR;
        BARW(barid);                              // pairwise handoff (2 warps only)
        if (fin) {
            float gate = fast_sigmoid(totR + redR[ridx] + xr);
            __stcg(&g_rh[(size_t)gbo * 512 + nn], gate * sh[bat * WS + nn]);
        }
        __syncthreads();
        if (tid == 0) bar_signal(grp, c, base + 2u * t + 1u);

        // ---- phase Z (local; hides barrier-1) ----
#pragma unroll
        for (int i = 0; i < 16; i++) a[i] = 0ull;
        mk44(wz, hh, a);
        float totZ = reduce16(a, l);
        if (kh == 1 && (l & 1) == 0) redZ[ridx] = totZ;

        bar_poll(grp, base + 2u * t + 1u);   // full sync covers redZ

        // ---- stage rh ----
        {
            int b = tid >> 7, q = (tid & 127) * 4;
            float4 v = __ldcg((const float4*)(g_rh + (size_t)(grp * 4 + b) * 512 + q));
            *(float4*)(srh + b * WS + q) = v;
        }
        float zv = 0.f;
        if (fin) zv = fast_sigmoid(totZ + redZ[ridx] + xz);
        __syncthreads();

        // ---- phase C ----
#pragma unroll
        for (int i = 0; i < 16; i++) a[i] = 0ull;
        mk44(wc, rr, a);
        float totC = reduce16(a, l);
        if (kh == 1 && (l & 1) == 0) redC[ridx] = totC;
        BARW(barid);                              // pairwise handoff
        float hnew = 0.f;
        if (fin) {
            float cand = fast_tanh(totC + redC[ridx] + xc);
            float hold = sh[bat * WS + nn];
            hnew = hold + zv * (cand - hold);
            __stcg(&g_h[(size_t)gbo * 512 + nn], hnew);
        }
        __syncthreads();
        if (tid == 0) bar_signal(grp, c, base + 2u * t + 2u);

        // off-critical-path: out store + next-step prefetch (overlap poll-2)
        if (fin) {
            out[(size_t)gbo * ((size_t)Lv * 512) + (size_t)t * 512 + nn] = hnew;
            if (has_last && t == Lv - 1)
                out[(size_t)Bv * Lv * 512 + (size_t)gbo * 512 + nn] = hnew;
            if (t < Lv - 1) {
                const float* p = g_pre + ((size_t)(t + 1) * 32 + gbo) * 1536;
                xr = __ldg(p + nn); xz = __ldg(p + 512 + nn); xc = __ldg(p + 1024 + nn);
            }
        }

        bar_poll(grp, base + 2u * t + 2u);

        // ---- restage h ----
        if (t < Lv - 1) {
            int b = tid >> 7, q = (tid & 127) * 4;
            float4 v = __ldcg((const float4*)(g_h + (size_t)(grp * 4 + b) * 512 + q));
            *(float4*)(sh + b * WS + q) = v;
            __syncthreads();
        }
    }
}

// ---------------- launch ----------------
extern "C" void kernel_launch(void* const* d_in, const int* in_sizes, int n_in,
                              void* d_out, int out_size) {
    const float* x      = (const float*)d_in[0];
    const float* init_h = (const float*)d_in[1];
    const float* W_ru   = (const float*)d_in[2];
    const float* b_ru   = (const float*)d_in[3];
    const float* W_c    = (const float*)d_in[4];
    const float* b_c    = (const float*)d_in[5];
    float* out = (float*)d_out;

    const int scan_smem = (3 * 32 * WS + 8 * WS + 3 * 128) * 4;  // 214,528 B
    cudaFuncSetAttribute(scan_kernel, cudaFuncAttributeMaxDynamicSharedMemorySize, scan_smem);

    int has_last = (out_size >= Bv * Lv * Hv + Bv * Hv) ? 1 : 0;

    gemm_pre<<<dim3(24, 512), 256>>>(x, W_ru, W_c, b_ru, b_c);
    scan_kernel<<<NGROUP * CPG, 512, scan_smem>>>(W_ru, W_c, init_h, out, has_last);
}

// round 13
// speedup vs baseline: 1.0424x; 1.0424x over previous
#include <cuda_runtime.h>
#include <cuda_bf16.h>
#include <cstdint>
#include <math.h>

typedef unsigned long long ull;

#define Bv 32
#define Lv 1024
#define Hv 512
#define NGROUP 8
#define CPG 16
#define WS 512

// ---------------- device scratch (no cudaMalloc allowed) ----------------
__device__ float g_pre[(size_t)Lv * Bv * 1536];   // [t][b][0..511]=r-pre, [512..1023]=z-pre, [1024..1535]=c-pre
__device__ float g_h [Bv * Hv];
__device__ float g_rh[Bv * Hv];
__device__ unsigned int g_flag[NGROUP * CPG * 32];   // one flag per CTA, own 128B line

// bf16 split operands for the HMMA projection GEMM
__device__ __nv_bfloat16 g_Ahi[(size_t)32768 * 512];
__device__ __nv_bfloat16 g_Alo[(size_t)32768 * 512];
__device__ __nv_bfloat16 g_Bhi[1536 * 512];
__device__ __nv_bfloat16 g_Blo[1536 * 512];

// ---------------- f32x2 helpers ----------------
__device__ __forceinline__ float2 unpack2(ull v) {
    float2 f; asm("mov.b64 {%0, %1}, %2;" : "=f"(f.x), "=f"(f.y) : "l"(v)); return f;
}
__device__ __forceinline__ void ffma2(ull& d, ull a, ull b) {
    asm("fma.rn.f32x2 %0, %1, %2, %0;" : "+l"(d) : "l"(a), "l"(b));
}
__device__ __forceinline__ float fast_sigmoid(float x) {
    x = fminf(fmaxf(x, -30.0f), 30.0f);
    return 1.0f / (1.0f + __expf(-x));
}
__device__ __forceinline__ float fast_tanh(float x) {
    x = fminf(fmaxf(x, -15.0f), 15.0f);
    float e = __expf(2.0f * x);
    return (e - 1.0f) / (e + 1.0f);
}
__device__ __forceinline__ unsigned smaddr(const void* p) {
    unsigned r;
    asm("{.reg .u64 t; cvta.to.shared.u64 t, %1; cvt.u32.u64 %0, t;}" : "=r"(r) : "l"(p));
    return r;
}

// ---------------- kernel 0: fp32 -> bf16 hi/lo split ----------------
__device__ __forceinline__ void split1(float v, __nv_bfloat16& h, __nv_bfloat16& l) {
    h = __float2bfloat16(v);
    l = __float2bfloat16(v - __bfloat162float(h));
}
__global__ void __launch_bounds__(256) prep_kernel(const float* __restrict__ x,
                                                   const float* __restrict__ W_ru,
                                                   const float* __restrict__ W_c) {
    size_t i = (size_t)blockIdx.x * 256 + threadIdx.x;   // covers 32768*512/4
    {
        size_t e = i * 4;
        float4 v = *(const float4*)(x + e);
        __nv_bfloat16 h0, l0, h1, l1, h2, l2, h3, l3;
        split1(v.x, h0, l0); split1(v.y, h1, l1); split1(v.z, h2, l2); split1(v.w, h3, l3);
        *(__nv_bfloat162*)(g_Ahi + e)     = __nv_bfloat162(h0, h1);
        *(__nv_bfloat162*)(g_Ahi + e + 2) = __nv_bfloat162(h2, h3);
        *(__nv_bfloat162*)(g_Alo + e)     = __nv_bfloat162(l0, l1);
        *(__nv_bfloat162*)(g_Alo + e + 2) = __nv_bfloat162(l2, l3);
    }
    if (i < (size_t)1536 * 512 / 4) {
        size_t e = i * 4;
        int n = (int)(e >> 9);
        int k = (int)(e & 511);
        const float* src = (n < 1024) ? (W_ru + (size_t)n * 1024 + 512 + k)
                                      : (W_c + (size_t)(n - 1024) * 1024 + 512 + k);
        float4 v = *(const float4*)src;
        __nv_bfloat16 h0, l0, h1, l1, h2, l2, h3, l3;
        split1(v.x, h0, l0); split1(v.y, h1, l1); split1(v.z, h2, l2); split1(v.w, h3, l3);
        *(__nv_bfloat162*)(g_Bhi + e)     = __nv_bfloat162(h0, h1);
        *(__nv_bfloat162*)(g_Bhi + e + 2) = __nv_bfloat162(h2, h3);
        *(__nv_bfloat162*)(g_Blo + e)     = __nv_bfloat162(l0, l1);
        *(__nv_bfloat162*)(g_Blo + e + 2) = __nv_bfloat162(l2, l3);
    }
}

// ---------------- kernel 1: HMMA bf16-split projection GEMM ----------------
// CTA tile 128m x 64n, 256 thr = 8 warps (4m x 2n), warp 32x32 via mma.m16n8k16.
// 3 passes (Ahi*Bhi, Ahi*Blo, Alo*Bhi) accumulate into the same fp32 frags.
#define ASTR 72   // bf16 per smem row (144B): ldmatrix banks r*4 mod 32 -> conflict-free

#define LDSM_X4(r0, r1, r2, r3, addr) \
    asm volatile("ldmatrix.sync.aligned.m8n8.x4.shared.b16 {%0,%1,%2,%3}, [%4];" \
        : "=r"(r0), "=r"(r1), "=r"(r2), "=r"(r3) : "r"(addr))

#define MMA_BF16(c, a, b0v, b1v) \
    asm volatile("mma.sync.aligned.m16n8k16.row.col.f32.bf16.bf16.f32 " \
        "{%0,%1,%2,%3}, {%4,%5,%6,%7}, {%8,%9}, {%0,%1,%2,%3};" \
        : "+f"((c)[0]), "+f"((c)[1]), "+f"((c)[2]), "+f"((c)[3]) \
        : "r"((a)[0]), "r"((a)[1]), "r"((a)[2]), "r"((a)[3]), "r"(b0v), "r"(b1v))

__global__ void __launch_bounds__(256) mma_pre(const float* __restrict__ b_ru,
                                               const float* __restrict__ b_c) {
    __shared__ __nv_bfloat16 smA[128 * ASTR];
    __shared__ __nv_bfloat16 smB[64 * ASTR];
    const int tid = threadIdx.x;
    const int n0 = blockIdx.x * 64;
    const int m0 = blockIdx.y * 128;
    const int w = tid >> 5, l = tid & 31;
    const int wm = w & 3, wn = w >> 2;

    float c[2][4][4];
#pragma unroll
    for (int i = 0; i < 2; i++)
#pragma unroll
        for (int j = 0; j < 4; j++)
#pragma unroll
            for (int k = 0; k < 4; k++) c[i][j][k] = 0.0f;

    const __nv_bfloat16* Asrc[3] = { g_Ahi, g_Ahi, g_Alo };
    const __nv_bfloat16* Bsrc[3] = { g_Bhi, g_Blo, g_Bhi };

    // ldmatrix row bases (chunk index swizzled per-row at use time)
    const uint32_t smA_u = smaddr(smA), smB_u = smaddr(smB);
    const int arow0 = wm * 32 + (l & 7) + ((l >> 3) & 1) * 8;   // + mf*16
    const int ahalf = (l >> 4) & 1;                              // k-half within frag
    const int brow0 = wn * 32 + (l & 7) + ((l >> 4) & 1) * 8;   // + nb*16
    const int bhalf = (l >> 3) & 1;

    // staging loader indices
    const int lrowA[4] = { (tid) >> 3, (tid + 256) >> 3, (tid + 512) >> 3, (tid + 768) >> 3 };
    const int lccA = tid & 7;
    const int lrowB[2] = { tid >> 3, (tid + 256) >> 3 };

    for (int p = 0; p < 3; p++) {
        const __nv_bfloat16* A = Asrc[p] + (size_t)m0 * 512;
        const __nv_bfloat16* B = Bsrc[p] + (size_t)n0 * 512;
        for (int s = 0; s < 8; s++) {
            const int k0 = s * 64;
            __syncthreads();
#pragma unroll
            for (int i = 0; i < 4; i++) {
                int row = lrowA[i], cc = lccA;
                *(uint4*)(smA + row * ASTR + ((cc ^ (row & 7)) * 8)) =
                    *(const uint4*)(A + (size_t)row * 512 + k0 + cc * 8);
            }
#pragma unroll
            for (int i = 0; i < 2; i++) {
                int row = lrowB[i], cc = lccA;
                *(uint4*)(smB + row * ASTR + ((cc ^ (row & 7)) * 8)) =
                    *(const uint4*)(B + (size_t)row * 512 + k0 + cc * 8);
            }
            __syncthreads();
#pragma unroll
            for (int kc = 0; kc < 4; kc++) {
                uint32_t a[2][4], b[2][4];
#pragma unroll
                for (int mf = 0; mf < 2; mf++) {
                    int row = arow0 + mf * 16;
                    int ch = (kc * 2 + ahalf) ^ (row & 7);
                    LDSM_X4(a[mf][0], a[mf][1], a[mf][2], a[mf][3],
                            smA_u + (uint32_t)(row * 144 + ch * 16));
                }
#pragma unroll
                for (int nb = 0; nb < 2; nb++) {
                    int row = brow0 + nb * 16;
                    int ch = (kc * 2 + bhalf) ^ (row & 7);
                    LDSM_X4(b[nb][0], b[nb][1], b[nb][2], b[nb][3],
                            smB_u + (uint32_t)(row * 144 + ch * 16));
                }
#pragma unroll
                for (int mf = 0; mf < 2; mf++)
#pragma unroll
                    for (int nf = 0; nf < 4; nf++)
                        MMA_BF16(c[mf][nf], a[mf], b[nf >> 1][(nf & 1) * 2],
                                 b[nf >> 1][(nf & 1) * 2 + 1]);
            }
        }
    }

    // epilogue: add bias, scatter to g_pre[t][b][n]
    const int g = l >> 2, tig = l & 3;
#pragma unroll
    for (int mf = 0; mf < 2; mf++) {
#pragma unroll
        for (int nf = 0; nf < 4; nf++) {
            int col = n0 + wn * 32 + nf * 8 + tig * 2;
            float bi0 = (col < 1024) ? b_ru[col] : b_c[col - 1024];
            float bi1 = (col < 1024) ? b_ru[col + 1] : b_c[col - 1023];
            int r0 = m0 + wm * 32 + mf * 16 + g;
            int r1 = r0 + 8;
            float2 v0 = make_float2(c[mf][nf][0] + bi0, c[mf][nf][1] + bi1);
            float2 v1 = make_float2(c[mf][nf][2] + bi0, c[mf][nf][3] + bi1);
            *(float2*)&g_pre[((size_t)(r0 & 1023) * 32 + (r0 >> 10)) * 1536 + col] = v0;
            *(float2*)&g_pre[((size_t)(r1 & 1023) * 32 + (r1 >> 10)) * 1536 + col] = v1;
        }
    }
}

// ---------------- group barrier ----------------
__device__ __forceinline__ void bar_signal(int grp, int c, unsigned target) {
    asm volatile("st.release.gpu.u32 [%0], %1;"
                 :: "l"(g_flag + ((size_t)(grp * CPG + c) * 32)), "r"(target) : "memory");
}
__device__ __forceinline__ void bar_poll(int grp, unsigned target) {
    if (threadIdx.x < CPG) {
        const unsigned* fp = g_flag + ((size_t)(grp * CPG + threadIdx.x) * 32);
        unsigned v;
        do {
            asm volatile("ld.acquire.gpu.u32 %0, [%1];" : "=r"(v) : "l"(fp) : "memory");
        } while ((int)(v - target) < 0);
    }
    __syncthreads();
}

// ---------------- scan microkernel (R11 proven) ----------------
__device__ __forceinline__ void mk44(const float* __restrict__ wb,
                                     const float* __restrict__ hb, ull* a) {
#pragma unroll
    for (int i = 0; i < 4; i++) {
        const int off = 64 * i;
        ull w0 = *(const ull*)(wb + off);
        ull w1 = *(const ull*)(wb + WS + off);
        ull w2 = *(const ull*)(wb + 2 * WS + off);
        ull w3 = *(const ull*)(wb + 3 * WS + off);
        ull h0 = *(const ull*)(hb + off);
        ull h1 = *(const ull*)(hb + WS + off);
        ull h2 = *(const ull*)(hb + 2 * WS + off);
        ull h3 = *(const ull*)(hb + 3 * WS + off);
        ffma2(a[0],  w0, h0); ffma2(a[1],  w0, h1); ffma2(a[2],  w0, h2); ffma2(a[3],  w0, h3);
        ffma2(a[4],  w1, h0); ffma2(a[5],  w1, h1); ffma2(a[6],  w1, h2); ffma2(a[7],  w1, h3);
        ffma2(a[8],  w2, h0); ffma2(a[9],  w2, h1); ffma2(a[10], w2, h2); ffma2(a[11], w2, h3);
        ffma2(a[12], w3, h0); ffma2(a[13], w3, h1); ffma2(a[14], w3, h2); ffma2(a[15], w3, h3);
    }
}
__device__ __forceinline__ float reduce16(const ull* a, int l) {
    float vals[16];
#pragma unroll
    for (int v = 0; v < 16; v++) { float2 f = unpack2(a[v]); vals[v] = f.x + f.y; }
#pragma unroll
    for (int i = 0; i < 8; i++) {
        float send = (l & 16) ? vals[i] : vals[i + 8];
        float recv = __shfl_xor_sync(0xffffffffu, send, 16);
        vals[i] = ((l & 16) ? vals[i + 8] : vals[i]) + recv;
    }
#pragma unroll
    for (int i = 0; i < 4; i++) {
        float send = (l & 8) ? vals[i] : vals[i + 4];
        float recv = __shfl_xor_sync(0xffffffffu, send, 8);
        vals[i] = ((l & 8) ? vals[i + 4] : vals[i]) + recv;
    }
#pragma unroll
    for (int i = 0; i < 2; i++) {
        float send = (l & 4) ? vals[i] : vals[i + 2];
        float recv = __shfl_xor_sync(0xffffffffu, send, 4);
        vals[i] = ((l & 4) ? vals[i + 2] : vals[i]) + recv;
    }
    {
        float send = (l & 2) ? vals[0] : vals[1];
        float recv = __shfl_xor_sync(0xffffffffu, send, 2);
        vals[0] = ((l & 2) ? vals[1] : vals[0]) + recv;
    }
    return vals[0] + __shfl_xor_sync(0xffffffffu, vals[0], 1);
}

// ---------------- kernel 2: persistent scan, r/z/cand split (R11 verbatim) ----------------
__global__ void __launch_bounds__(512, 1) scan_kernel(const float* __restrict__ W_ru,
                                                      const float* __restrict__ W_c,
                                                      const float* __restrict__ init_h,
                                                      float* __restrict__ out,
                                                      int has_last) {
    extern __shared__ float sm[];
    float* sWr = sm;
    float* sWz = sWr + 32 * WS;
    float* sWc = sWz + 32 * WS;
    float* sh  = sWc + 32 * WS;
    float* srh = sh + 4 * WS;
    float* redR = srh + 4 * WS;
    float* redZ = redR + 128;
    float* redC = redZ + 128;
    __shared__ unsigned sBase;

    const int tid = threadIdx.x;
    const int w = tid >> 5, l = tid & 31;
    const int rg = w >> 1, kh = w & 1;
    const int grp = blockIdx.x >> 4;
    const int c   = blockIdx.x & 15;

    if (tid == 0) sBase = g_flag[(size_t)(grp * CPG + c) * 32];

    for (int i = tid; i < 32 * 128; i += 512) {
        int r = i >> 7, q = (i & 127) * 4;
        *(float4*)(sWr + r * WS + q) = *(const float4*)(W_ru + (size_t)(c * 32 + r) * 1024 + q);
        *(float4*)(sWz + r * WS + q) = *(const float4*)(W_ru + (size_t)(512 + c * 32 + r) * 1024 + q);
        *(float4*)(sWc + r * WS + q) = *(const float4*)(W_c + (size_t)(c * 32 + r) * 1024 + q);
    }
    {
        int b = tid >> 7, q = (tid & 127) * 4;
        *(float4*)(sh + b * WS + q) = *(const float4*)(init_h + (size_t)(grp * 4 + b) * 512 + q);
    }
    __syncthreads();
    const unsigned base = sBase;

    const int oidx = (l >> 1) & 15;
    const int row_local = rg * 4 + (oidx >> 2);
    const int bat = oidx & 3;
    const int nn  = c * 32 + row_local;
    const int gbo = grp * 4 + bat;
    const bool fin = (kh == 0) && ((l & 1) == 0);
    const int ridx = rg * 16 + oidx;

    const float* wr = sWr + (rg * 4) * WS + kh * 256 + 2 * l;
    const float* wz = sWz + (rg * 4) * WS + kh * 256 + 2 * l;
    const float* wc = sWc + (rg * 4) * WS + kh * 256 + 2 * l;
    const float* hh = sh + kh * 256 + 2 * l;
    const float* rr = srh + kh * 256 + 2 * l;

    float xr = 0.f, xz = 0.f, xc = 0.f;
    if (fin) {
        const float* p = g_pre + (size_t)gbo * 1536;
        xr = __ldg(p + nn); xz = __ldg(p + 512 + nn); xc = __ldg(p + 1024 + nn);
    }

    for (int t = 0; t < Lv; t++) {
        // ---- phase R ----
        ull a[16];
#pragma unroll
        for (int i = 0; i < 16; i++) a[i] = 0ull;
        mk44(wr, hh, a);
        float totR = reduce16(a, l);
        if (kh == 1 && (l & 1) == 0) redR[ridx] = totR;
        __syncthreads();
        if (fin) {
            float gate = fast_sigmoid(totR + redR[ridx] + xr);
            __stcg(&g_rh[(size_t)gbo * 512 + nn], gate * sh[bat * WS + nn]);
        }
        __syncthreads();
        if (tid == 0) bar_signal(grp, c, base + 2u * t + 1u);

        // ---- phase Z (local; hides barrier-1) ----
#pragma unroll
        for (int i = 0; i < 16; i++) a[i] = 0ull;
        mk44(wz, hh, a);
        float totZ = reduce16(a, l);
        if (kh == 1 && (l & 1) == 0) redZ[ridx] = totZ;

        bar_poll(grp, base + 2u * t + 1u);

        // ---- stage rh ----
        {
            int b = tid >> 7, q = (tid & 127) * 4;
            float4 v = __ldcg((const float4*)(g_rh + (size_t)(grp * 4 + b) * 512 + q));
            *(float4*)(srh + b * WS + q) = v;
        }
        float zv = 0.f;
        if (fin) zv = fast_sigmoid(totZ + redZ[ridx] + xz);
        __syncthreads();

        // ---- phase C ----
#pragma unroll
        for (int i = 0; i < 16; i++) a[i] = 0ull;
        mk44(wc, rr, a);
        float totC = reduce16(a, l);
        if (kh == 1 && (l & 1) == 0) redC[ridx] = totC;
        __syncthreads();
        float hnew = 0.f;
        if (fin) {
            float cand = fast_tanh(totC + redC[ridx] + xc);
            float hold = sh[bat * WS + nn];
            hnew = hold + zv * (cand - hold);
            __stcg(&g_h[(size_t)gbo * 512 + nn], hnew);
        }
        __syncthreads();
        if (tid == 0) bar_signal(grp, c, base + 2u * t + 2u);

        if (fin) {
            out[(size_t)gbo * ((size_t)Lv * 512) + (size_t)t * 512 + nn] = hnew;
            if (has_last && t == Lv - 1)
                out[(size_t)Bv * Lv * 512 + (size_t)gbo * 512 + nn] = hnew;
            if (t < Lv - 1) {
                const float* p = g_pre + ((size_t)(t + 1) * 32 + gbo) * 1536;
                xr = __ldg(p + nn); xz = __ldg(p + 512 + nn); xc = __ldg(p + 1024 + nn);
            }
        }

        bar_poll(grp, base + 2u * t + 2u);

        // ---- restage h ----
        if (t < Lv - 1) {
            int b = tid >> 7, q = (tid & 127) * 4;
            float4 v = __ldcg((const float4*)(g_h + (size_t)(grp * 4 + b) * 512 + q));
            *(float4*)(sh + b * WS + q) = v;
            __syncthreads();
        }
    }
}

// ---------------- launch ----------------
extern "C" void kernel_launch(void* const* d_in, const int* in_sizes, int n_in,
                              void* d_out, int out_size) {
    const float* x      = (const float*)d_in[0];
    const float* init_h = (const float*)d_in[1];
    const float* W_ru   = (const float*)d_in[2];
    const float* b_ru   = (const float*)d_in[3];
    const float* W_c    = (const float*)d_in[4];
    const float* b_c    = (const float*)d_in[5];
    float* out = (float*)d_out;

    const int scan_smem = (3 * 32 * WS + 8 * WS + 3 * 128) * 4;  // 214,528 B
    cudaFuncSetAttribute(scan_kernel, cudaFuncAttributeMaxDynamicSharedMemorySize, scan_smem);

    int has_last = (out_size >= Bv * Lv * Hv + Bv * Hv) ? 1 : 0;

    prep_kernel<<<16384, 256>>>(x, W_ru, W_c);
    mma_pre<<<dim3(24, 256), 256>>>(b_ru, b_c);
    scan_kernel<<<NGROUP * CPG, 512, scan_smem>>>(W_ru, W_c, init_h, out, has_last);
}

// round 14
// speedup vs baseline: 1.0551x; 1.0122x over previous
#include <cuda_runtime.h>
#include <cuda_bf16.h>
#include <cstdint>
#include <math.h>

typedef unsigned long long ull;

#define Bv 32
#define Lv 1024
#define Hv 512
#define NGROUP 8
#define CPG 16
#define WS 512

// ---------------- device scratch (no cudaMalloc allowed) ----------------
__device__ float g_pre[(size_t)Lv * Bv * 1536];   // [t][b][0..511]=r-pre, [512..1023]=z-pre, [1024..1535]=c-pre
__device__ float g_h [Bv * Hv];
__device__ float g_rh[Bv * Hv];
__device__ unsigned int g_flag[NGROUP * CPG * 32];   // one flag per CTA, own 128B line

// bf16 split operands for the HMMA projection GEMM
__device__ __nv_bfloat16 g_Ahi[(size_t)32768 * 512];
__device__ __nv_bfloat16 g_Alo[(size_t)32768 * 512];
__device__ __nv_bfloat16 g_Bhi[1536 * 512];
__device__ __nv_bfloat16 g_Blo[1536 * 512];

// ---------------- f32x2 helpers ----------------
__device__ __forceinline__ float2 unpack2(ull v) {
    float2 f; asm("mov.b64 {%0, %1}, %2;" : "=f"(f.x), "=f"(f.y) : "l"(v)); return f;
}
__device__ __forceinline__ void ffma2(ull& d, ull a, ull b) {
    asm("fma.rn.f32x2 %0, %1, %2, %0;" : "+l"(d) : "l"(a), "l"(b));
}
__device__ __forceinline__ float fast_sigmoid(float x) {
    x = fminf(fmaxf(x, -30.0f), 30.0f);
    return 1.0f / (1.0f + __expf(-x));
}
__device__ __forceinline__ float fast_tanh(float x) {
    x = fminf(fmaxf(x, -15.0f), 15.0f);
    float e = __expf(2.0f * x);
    return (e - 1.0f) / (e + 1.0f);
}
__device__ __forceinline__ unsigned smaddr(const void* p) {
    unsigned r;
    asm("{.reg .u64 t; cvta.to.shared.u64 t, %1; cvt.u32.u64 %0, t;}" : "=r"(r) : "l"(p));
    return r;
}

// ---------------- kernel 0: fp32 -> bf16 hi/lo split ----------------
__device__ __forceinline__ void split1(float v, __nv_bfloat16& h, __nv_bfloat16& l) {
    h = __float2bfloat16(v);
    l = __float2bfloat16(v - __bfloat162float(h));
}
__global__ void __launch_bounds__(256) prep_kernel(const float* __restrict__ x,
                                                   const float* __restrict__ W_ru,
                                                   const float* __restrict__ W_c) {
    size_t i = (size_t)blockIdx.x * 256 + threadIdx.x;   // covers 32768*512/4
    {
        size_t e = i * 4;
        float4 v = *(const float4*)(x + e);
        __nv_bfloat16 h0, l0, h1, l1, h2, l2, h3, l3;
        split1(v.x, h0, l0); split1(v.y, h1, l1); split1(v.z, h2, l2); split1(v.w, h3, l3);
        *(__nv_bfloat162*)(g_Ahi + e)     = __nv_bfloat162(h0, h1);
        *(__nv_bfloat162*)(g_Ahi + e + 2) = __nv_bfloat162(h2, h3);
        *(__nv_bfloat162*)(g_Alo + e)     = __nv_bfloat162(l0, l1);
        *(__nv_bfloat162*)(g_Alo + e + 2) = __nv_bfloat162(l2, l3);
    }
    if (i < (size_t)1536 * 512 / 4) {
        size_t e = i * 4;
        int n = (int)(e >> 9);
        int k = (int)(e & 511);
        const float* src = (n < 1024) ? (W_ru + (size_t)n * 1024 + 512 + k)
                                      : (W_c + (size_t)(n - 1024) * 1024 + 512 + k);
        float4 v = *(const float4*)src;
        __nv_bfloat16 h0, l0, h1, l1, h2, l2, h3, l3;
        split1(v.x, h0, l0); split1(v.y, h1, l1); split1(v.z, h2, l2); split1(v.w, h3, l3);
        *(__nv_bfloat162*)(g_Bhi + e)     = __nv_bfloat162(h0, h1);
        *(__nv_bfloat162*)(g_Bhi + e + 2) = __nv_bfloat162(h2, h3);
        *(__nv_bfloat162*)(g_Blo + e)     = __nv_bfloat162(l0, l1);
        *(__nv_bfloat162*)(g_Blo + e + 2) = __nv_bfloat162(l2, l3);
    }
}

// ---------------- kernel 1: HMMA bf16-split GEMM, cp.async 3-stage pipeline ----------------
// CTA tile 128m x 64n, 256 thr = 8 warps (4m x 2n), warp 32x32 via mma.m16n8k16.
// 3 passes (Ahi*Bhi, Ahi*Blo, Alo*Bhi) x 8 K-stages = 24 flat stages, triple-buffered.
#define ASTR 72                 // bf16 per smem row (144B)
#define ABUF_B (128 * 144)      // 18432 B per A buffer
#define BBUF_B (64 * 144)       // 9216 B per B buffer
#define MMA_SMEM (3 * (ABUF_B + BBUF_B))   // 82944 B

#define LDSM_X4(r0, r1, r2, r3, addr) \
    asm volatile("ldmatrix.sync.aligned.m8n8.x4.shared.b16 {%0,%1,%2,%3}, [%4];" \
        : "=r"(r0), "=r"(r1), "=r"(r2), "=r"(r3) : "r"(addr))

#define MMA_BF16(c, a, b0v, b1v) \
    asm volatile("mma.sync.aligned.m16n8k16.row.col.f32.bf16.bf16.f32 " \
        "{%0,%1,%2,%3}, {%4,%5,%6,%7}, {%8,%9}, {%0,%1,%2,%3};" \
        : "+f"((c)[0]), "+f"((c)[1]), "+f"((c)[2]), "+f"((c)[3]) \
        : "r"((a)[0]), "r"((a)[1]), "r"((a)[2]), "r"((a)[3]), "r"(b0v), "r"(b1v))

#define CP_ASYNC16(sdst, gsrc) \
    asm volatile("cp.async.cg.shared.global [%0], [%1], 16;" :: "r"(sdst), "l"(gsrc))
#define CP_COMMIT() asm volatile("cp.async.commit_group;" ::: "memory")
#define CP_WAIT1()  asm volatile("cp.async.wait_group 1;" ::: "memory")
#define CP_WAIT0()  asm volatile("cp.async.wait_group 0;" ::: "memory")

__global__ void __launch_bounds__(256) mma_pre(const float* __restrict__ b_ru,
                                               const float* __restrict__ b_c) {
    extern __shared__ __nv_bfloat16 dsm[];
    const uint32_t smA_u = smaddr(dsm);
    const uint32_t smB_u = smA_u + 3 * ABUF_B;
    const int tid = threadIdx.x;
    const int n0 = blockIdx.x * 64;
    const int m0 = blockIdx.y * 128;
    const int w = tid >> 5, l = tid & 31;
    const int wm = w & 3, wn = w >> 2;

    float c[2][4][4];
#pragma unroll
    for (int i = 0; i < 2; i++)
#pragma unroll
        for (int j = 0; j < 4; j++)
#pragma unroll
            for (int k = 0; k < 4; k++) c[i][j][k] = 0.0f;

    const __nv_bfloat16* Apass[3] = { g_Ahi + (size_t)m0 * 512, g_Ahi + (size_t)m0 * 512,
                                      g_Alo + (size_t)m0 * 512 };
    const __nv_bfloat16* Bpass[3] = { g_Bhi + (size_t)n0 * 512, g_Blo + (size_t)n0 * 512,
                                      g_Bhi + (size_t)n0 * 512 };

    // loader: 4 A-chunks + 2 B-chunks of 16B per thread per stage
    const int lcc = tid & 7;

    // ldmatrix fragment bases (verified R13 mapping)
    const int arow0 = wm * 32 + (l & 7) + ((l >> 3) & 1) * 8;   // + mf*16
    const int ahalf = (l >> 4) & 1;
    const int brow0 = wn * 32 + (l & 7) + ((l >> 4) & 1) * 8;   // + nb*16
    const int bhalf = (l >> 3) & 1;

#define STAGE_LOAD(it, buf) do {                                                        \
    int _p = (it) >> 3, _k0 = ((it) & 7) * 64;                                          \
    const __nv_bfloat16* _A = Apass[_p] + _k0;                                          \
    const __nv_bfloat16* _B = Bpass[_p] + _k0;                                          \
    uint32_t _ab = smA_u + (buf) * ABUF_B;                                              \
    uint32_t _bb = smB_u + (buf) * BBUF_B;                                              \
    _Pragma("unroll")                                                                   \
    for (int _i = 0; _i < 4; _i++) {                                                    \
        int _row = (tid + 256 * _i) >> 3;                                               \
        CP_ASYNC16(_ab + (uint32_t)(_row * 144 + ((lcc ^ (_row & 7)) * 16)),            \
                   _A + (size_t)_row * 512 + lcc * 8);                                  \
    }                                                                                   \
    _Pragma("unroll")                                                                   \
    for (int _i = 0; _i < 2; _i++) {                                                    \
        int _row = (tid + 256 * _i) >> 3;                                               \
        CP_ASYNC16(_bb + (uint32_t)(_row * 144 + ((lcc ^ (_row & 7)) * 16)),            \
                   _B + (size_t)_row * 512 + lcc * 8);                                  \
    }                                                                                   \
} while (0)

    STAGE_LOAD(0, 0); CP_COMMIT();
    STAGE_LOAD(1, 1); CP_COMMIT();

    int buf = 0;
    for (int it = 0; it < 24; it++) {
        if (it < 23) { CP_WAIT1(); } else { CP_WAIT0(); }
        __syncthreads();
        if (it + 2 < 24) {
            int nb = buf + 2; if (nb >= 3) nb -= 3;
            STAGE_LOAD(it + 2, nb);
            CP_COMMIT();
        }
        const uint32_t ab = smA_u + buf * ABUF_B;
        const uint32_t bb = smB_u + buf * BBUF_B;
#pragma unroll
        for (int kc = 0; kc < 4; kc++) {
            uint32_t a[2][4], b[2][4];
#pragma unroll
            for (int mf = 0; mf < 2; mf++) {
                int row = arow0 + mf * 16;
                int ch = (kc * 2 + ahalf) ^ (row & 7);
                LDSM_X4(a[mf][0], a[mf][1], a[mf][2], a[mf][3],
                        ab + (uint32_t)(row * 144 + ch * 16));
            }
#pragma unroll
            for (int nb2 = 0; nb2 < 2; nb2++) {
                int row = brow0 + nb2 * 16;
                int ch = (kc * 2 + bhalf) ^ (row & 7);
                LDSM_X4(b[nb2][0], b[nb2][1], b[nb2][2], b[nb2][3],
                        bb + (uint32_t)(row * 144 + ch * 16));
            }
#pragma unroll
            for (int mf = 0; mf < 2; mf++)
#pragma unroll
                for (int nf = 0; nf < 4; nf++)
                    MMA_BF16(c[mf][nf], a[mf], b[nf >> 1][(nf & 1) * 2],
                             b[nf >> 1][(nf & 1) * 2 + 1]);
        }
        if (++buf == 3) buf = 0;
    }

    // epilogue: add bias, scatter to g_pre[t][b][n]
    const int g = l >> 2, tig = l & 3;
#pragma unroll
    for (int mf = 0; mf < 2; mf++) {
#pragma unroll
        for (int nf = 0; nf < 4; nf++) {
            int col = n0 + wn * 32 + nf * 8 + tig * 2;
            float bi0 = (col < 1024) ? b_ru[col] : b_c[col - 1024];
            float bi1 = (col < 1024) ? b_ru[col + 1] : b_c[col - 1023];
            int r0 = m0 + wm * 32 + mf * 16 + g;
            int r1 = r0 + 8;
            float2 v0 = make_float2(c[mf][nf][0] + bi0, c[mf][nf][1] + bi1);
            float2 v1 = make_float2(c[mf][nf][2] + bi0, c[mf][nf][3] + bi1);
            *(float2*)&g_pre[((size_t)(r0 & 1023) * 32 + (r0 >> 10)) * 1536 + col] = v0;
            *(float2*)&g_pre[((size_t)(r1 & 1023) * 32 + (r1 >> 10)) * 1536 + col] = v1;
        }
    }
}

// ---------------- group barrier ----------------
__device__ __forceinline__ void bar_signal(int grp, int c, unsigned target) {
    asm volatile("st.release.gpu.u32 [%0], %1;"
                 :: "l"(g_flag + ((size_t)(grp * CPG + c) * 32)), "r"(target) : "memory");
}
__device__ __forceinline__ void bar_poll(int grp, unsigned target) {
    if (threadIdx.x < CPG) {
        const unsigned* fp = g_flag + ((size_t)(grp * CPG + threadIdx.x) * 32);
        unsigned v;
        do {
            asm volatile("ld.acquire.gpu.u32 %0, [%1];" : "=r"(v) : "l"(fp) : "memory");
        } while ((int)(v - target) < 0);
    }
    __syncthreads();
}

// ---------------- scan microkernel (R11 proven) ----------------
__device__ __forceinline__ void mk44(const float* __restrict__ wb,
                                     const float* __restrict__ hb, ull* a) {
#pragma unroll
    for (int i = 0; i < 4; i++) {
        const int off = 64 * i;
        ull w0 = *(const ull*)(wb + off);
        ull w1 = *(const ull*)(wb + WS + off);
        ull w2 = *(const ull*)(wb + 2 * WS + off);
        ull w3 = *(const ull*)(wb + 3 * WS + off);
        ull h0 = *(const ull*)(hb + off);
        ull h1 = *(const ull*)(hb + WS + off);
        ull h2 = *(const ull*)(hb + 2 * WS + off);
        ull h3 = *(const ull*)(hb + 3 * WS + off);
        ffma2(a[0],  w0, h0); ffma2(a[1],  w0, h1); ffma2(a[2],  w0, h2); ffma2(a[3],  w0, h3);
        ffma2(a[4],  w1, h0); ffma2(a[5],  w1, h1); ffma2(a[6],  w1, h2); ffma2(a[7],  w1, h3);
        ffma2(a[8],  w2, h0); ffma2(a[9],  w2, h1); ffma2(a[10], w2, h2); ffma2(a[11], w2, h3);
        ffma2(a[12], w3, h0); ffma2(a[13], w3, h1); ffma2(a[14], w3, h2); ffma2(a[15], w3, h3);
    }
}
__device__ __forceinline__ float reduce16(const ull* a, int l) {
    float vals[16];
#pragma unroll
    for (int v = 0; v < 16; v++) { float2 f = unpack2(a[v]); vals[v] = f.x + f.y; }
#pragma unroll
    for (int i = 0; i < 8; i++) {
        float send = (l & 16) ? vals[i] : vals[i + 8];
        float recv = __shfl_xor_sync(0xffffffffu, send, 16);
        vals[i] = ((l & 16) ? vals[i + 8] : vals[i]) + recv;
    }
#pragma unroll
    for (int i = 0; i < 4; i++) {
        float send = (l & 8) ? vals[i] : vals[i + 4];
        float recv = __shfl_xor_sync(0xffffffffu, send, 8);
        vals[i] = ((l & 8) ? vals[i + 4] : vals[i]) + recv;
    }
#pragma unroll
    for (int i = 0; i < 2; i++) {
        float send = (l & 4) ? vals[i] : vals[i + 2];
        float recv = __shfl_xor_sync(0xffffffffu, send, 4);
        vals[i] = ((l & 4) ? vals[i + 2] : vals[i]) + recv;
    }
    {
        float send = (l & 2) ? vals[0] : vals[1];
        float recv = __shfl_xor_sync(0xffffffffu, send, 2);
        vals[0] = ((l & 2) ? vals[1] : vals[0]) + recv;
    }
    return vals[0] + __shfl_xor_sync(0xffffffffu, vals[0], 1);
}

// ---------------- kernel 2: persistent scan, r/z/cand split (R11 verbatim) ----------------
__global__ void __launch_bounds__(512, 1) scan_kernel(const float* __restrict__ W_ru,
                                                      const float* __restrict__ W_c,
                                                      const float* __restrict__ init_h,
                                                      float* __restrict__ out,
                                                      int has_last) {
    extern __shared__ float sm[];
    float* sWr = sm;
    float* sWz = sWr + 32 * WS;
    float* sWc = sWz + 32 * WS;
    float* sh  = sWc + 32 * WS;
    float* srh = sh + 4 * WS;
    float* redR = srh + 4 * WS;
    float* redZ = redR + 128;
    float* redC = redZ + 128;
    __shared__ unsigned sBase;

    const int tid = threadIdx.x;
    const int w = tid >> 5, l = tid & 31;
    const int rg = w >> 1, kh = w & 1;
    const int grp = blockIdx.x >> 4;
    const int c   = blockIdx.x & 15;

    if (tid == 0) sBase = g_flag[(size_t)(grp * CPG + c) * 32];

    for (int i = tid; i < 32 * 128; i += 512) {
        int r = i >> 7, q = (i & 127) * 4;
        *(float4*)(sWr + r * WS + q) = *(const float4*)(W_ru + (size_t)(c * 32 + r) * 1024 + q);
        *(float4*)(sWz + r * WS + q) = *(const float4*)(W_ru + (size_t)(512 + c * 32 + r) * 1024 + q);
        *(float4*)(sWc + r * WS + q) = *(const float4*)(W_c + (size_t)(c * 32 + r) * 1024 + q);
    }
    {
        int b = tid >> 7, q = (tid & 127) * 4;
        *(float4*)(sh + b * WS + q) = *(const float4*)(init_h + (size_t)(grp * 4 + b) * 512 + q);
    }
    __syncthreads();
    const unsigned base = sBase;

    const int oidx = (l >> 1) & 15;
    const int row_local = rg * 4 + (oidx >> 2);
    const int bat = oidx & 3;
    const int nn  = c * 32 + row_local;
    const int gbo = grp * 4 + bat;
    const bool fin = (kh == 0) && ((l & 1) == 0);
    const int ridx = rg * 16 + oidx;

    const float* wr = sWr + (rg * 4) * WS + kh * 256 + 2 * l;
    const float* wz = sWz + (rg * 4) * WS + kh * 256 + 2 * l;
    const float* wc = sWc + (rg * 4) * WS + kh * 256 + 2 * l;
    const float* hh = sh + kh * 256 + 2 * l;
    const float* rr = srh + kh * 256 + 2 * l;

    float xr = 0.f, xz = 0.f, xc = 0.f;
    if (fin) {
        const float* p = g_pre + (size_t)gbo * 1536;
        xr = __ldg(p + nn); xz = __ldg(p + 512 + nn); xc = __ldg(p + 1024 + nn);
    }

    for (int t = 0; t < Lv; t++) {
        // ---- phase R ----
        ull a[16];
#pragma unroll
        for (int i = 0; i < 16; i++) a[i] = 0ull;
        mk44(wr, hh, a);
        float totR = reduce16(a, l);
        if (kh == 1 && (l & 1) == 0) redR[ridx] = totR;
        __syncthreads();
        if (fin) {
            float gate = fast_sigmoid(totR + redR[ridx] + xr);
            __stcg(&g_rh[(size_t)gbo * 512 + nn], gate * sh[bat * WS + nn]);
        }
        __syncthreads();
        if (tid == 0) bar_signal(grp, c, base + 2u * t + 1u);

        // ---- phase Z (local; hides barrier-1) ----
#pragma unroll
        for (int i = 0; i < 16; i++) a[i] = 0ull;
        mk44(wz, hh, a);
        float totZ = reduce16(a, l);
        if (kh == 1 && (l & 1) == 0) redZ[ridx] = totZ;

        bar_poll(grp, base + 2u * t + 1u);

        // ---- stage rh ----
        {
            int b = tid >> 7, q = (tid & 127) * 4;
            float4 v = __ldcg((const float4*)(g_rh + (size_t)(grp * 4 + b) * 512 + q));
            *(float4*)(srh + b * WS + q) = v;
        }
        float zv = 0.f;
        if (fin) zv = fast_sigmoid(totZ + redZ[ridx] + xz);
        __syncthreads();

        // ---- phase C ----
#pragma unroll
        for (int i = 0; i < 16; i++) a[i] = 0ull;
        mk44(wc, rr, a);
        float totC = reduce16(a, l);
        if (kh == 1 && (l & 1) == 0) redC[ridx] = totC;
        __syncthreads();
        float hnew = 0.f;
        if (fin) {
            float cand = fast_tanh(totC + redC[ridx] + xc);
            float hold = sh[bat * WS + nn];
            hnew = hold + zv * (cand - hold);
            __stcg(&g_h[(size_t)gbo * 512 + nn], hnew);
        }
        __syncthreads();
        if (tid == 0) bar_signal(grp, c, base + 2u * t + 2u);

        if (fin) {
            out[(size_t)gbo * ((size_t)Lv * 512) + (size_t)t * 512 + nn] = hnew;
            if (has_last && t == Lv - 1)
                out[(size_t)Bv * Lv * 512 + (size_t)gbo * 512 + nn] = hnew;
            if (t < Lv - 1) {
                const float* p = g_pre + ((size_t)(t + 1) * 32 + gbo) * 1536;
                xr = __ldg(p + nn); xz = __ldg(p + 512 + nn); xc = __ldg(p + 1024 + nn);
            }
        }

        bar_poll(grp, base + 2u * t + 2u);

        // ---- restage h ----
        if (t < Lv - 1) {
            int b = tid >> 7, q = (tid & 127) * 4;
            float4 v = __ldcg((const float4*)(g_h + (size_t)(grp * 4 + b) * 512 + q));
            *(float4*)(sh + b * WS + q) = v;
            __syncthreads();
        }
    }
}

// ---------------- launch ----------------
extern "C" void kernel_launch(void* const* d_in, const int* in_sizes, int n_in,
                              void* d_out, int out_size) {
    const float* x      = (const float*)d_in[0];
    const float* init_h = (const float*)d_in[1];
    const float* W_ru   = (const float*)d_in[2];
    const float* b_ru   = (const float*)d_in[3];
    const float* W_c    = (const float*)d_in[4];
    const float* b_c    = (const float*)d_in[5];
    float* out = (float*)d_out;

    const int scan_smem = (3 * 32 * WS + 8 * WS + 3 * 128) * 4;  // 214,528 B
    cudaFuncSetAttribute(scan_kernel, cudaFuncAttributeMaxDynamicSharedMemorySize, scan_smem);
    cudaFuncSetAttribute(mma_pre, cudaFuncAttributeMaxDynamicSharedMemorySize, MMA_SMEM);

    int has_last = (out_size >= Bv * Lv * Hv + Bv * Hv) ? 1 : 0;

    prep_kernel<<<16384, 256>>>(x, W_ru, W_c);
    mma_pre<<<dim3(24, 256), 256, MMA_SMEM>>>(b_ru, b_c);
    scan_kernel<<<NGROUP * CPG, 512, scan_smem>>>(W_ru, W_c, init_h, out, has_last);
}